// round 16
// baseline (speedup 1.0000x reference)
#include <cuda_runtime.h>
#include <cuda_fp16.h>
#include <math.h>

// ---------------- problem constants ----------------
#define NB 2
#define NV 3
#define NC 32
#define ND 48
#define NH 128
#define NW 160
#define NHW (NH*NW)          // 20480

typedef unsigned long long ull;

// ---------------- device scratch ----------------
// Feature layout: (V, B, cg=8, H, W, 4ch) fp32, pixel stride 16B
__device__ __align__(128) float g_featT[(size_t)NV*NB*NHW*NC];
// Variance volume fp16: (B, cg=8, D, H, W) x 4ch packed in uint2 (2x half2)
__device__ __align__(128) uint2 g_varH[(size_t)NB*8*ND*NHW];
__device__ __align__(16) float g_cost[(size_t)NB*ND*NHW];
__device__ float g_rot[NB][2][9];
__device__ float g_trans[NB][2][3];
// conv weights as float2 per (cg,chp,kh,kw,kd): [(cg*2+chp)*27 + (kh*3+kw)*3 + kd]
__device__ __align__(16) float g_wcf[864];
__device__ float g_bias;

// ---------------- packed f32x2 helpers ----------------
// In-place accumulate: dst==src3 guaranteed -> no register-pair shuffle MOVs.
__device__ __forceinline__ void fma2a(ull& c, ull a, ull b) {
    asm("fma.rn.f32x2 %0, %1, %2, %0;" : "+l"(c) : "l"(a), "l"(b));
}
__device__ __forceinline__ void add2a(ull& c, ull a) {
    asm("add.rn.f32x2 %0, %0, %1;" : "+l"(c) : "l"(a));
}
__device__ __forceinline__ ull fma2(ull a, ull b, ull c) {
    ull d; asm("fma.rn.f32x2 %0, %1, %2, %3;" : "=l"(d) : "l"(a), "l"(b), "l"(c)); return d;
}
__device__ __forceinline__ ull mul2(ull a, ull b) {
    ull d; asm("mul.rn.f32x2 %0, %1, %2;" : "=l"(d) : "l"(a), "l"(b)); return d;
}
__device__ __forceinline__ ull dup2(float f) {
    ull d; int r = __float_as_int(f);
    asm("mov.b64 %0, {%1, %1};" : "=l"(d) : "r"(r)); return d;
}
__device__ __forceinline__ float sum2(ull v) {
    int lo, hi; asm("mov.b64 {%0, %1}, %2;" : "=r"(lo), "=r"(hi) : "l"(v));
    return __int_as_float(lo) + __int_as_float(hi);
}
// f32x2 (ull) -> half2 bits
__device__ __forceinline__ unsigned pkh2(ull v) {
    float lo, hi;
    asm("mov.b64 {%0, %1}, %2;" : "=f"(lo), "=f"(hi) : "l"(v));
    unsigned r;
    asm("cvt.rn.f16x2.f32 %0, %1, %2;" : "=r"(r) : "f"(hi), "f"(lo));
    return r;
}
// half2 bits -> f32x2 (ull)
__device__ __forceinline__ ull h2f2(unsigned h) {
    float lo, hi;
    asm("{ .reg .f16 l, u; mov.b32 {l, u}, %2; cvt.f32.f16 %0, l; cvt.f32.f16 %1, u; }"
        : "=f"(lo), "=f"(hi) : "r"(h));
    ull d; asm("mov.b64 %0, {%1, %2};" : "=l"(d) : "f"(lo), "f"(hi));
    return d;
}
#define NEGMASK 0x8000000080000000ULL
#define INV3P   0x3eaaaaab3eaaaaabULL   // (1/3, 1/3)

// ---------------- prep: proj @ inv(ref_proj), weight relayout ----------------
__global__ void prep_kernel(const float* __restrict__ proj,
                            const float* __restrict__ rw,
                            const float* __restrict__ rb) {
    int tid = threadIdx.x;
    // rw layout (1,C,3,3,3): rw[c*27 + kd*9 + kh*3 + kw], c = cg*4 + chp*2 + lane
    for (int i = tid; i < 27*NC; i += blockDim.x) {
        int c = i / 27, k = i - c*27;
        int kd = k / 9, kh = (k - kd*9) / 3, kw = k % 3;
        int cg = c >> 2, chp = (c >> 1) & 1, lane = c & 1;
        g_wcf[(((cg*2 + chp)*27) + (kh*3 + kw)*3 + kd)*2 + lane] = rw[i];
    }
    if (tid == 0) g_bias = rb[0];
    if (tid < NB) {
        int b = tid;
        const float* refp = proj + ((size_t)b*NV + 0)*16;
        double a[4][8];
        for (int r = 0; r < 4; r++)
            for (int c2 = 0; c2 < 4; c2++) {
                a[r][c2] = (double)refp[r*4+c2];
                a[r][4+c2] = (r == c2) ? 1.0 : 0.0;
            }
        for (int col = 0; col < 4; col++) {
            int p = col; double best = fabs(a[col][col]);
            for (int r = col+1; r < 4; r++) {
                double v = fabs(a[r][col]);
                if (v > best) { best = v; p = r; }
            }
            if (p != col)
                for (int c2 = 0; c2 < 8; c2++) {
                    double t = a[col][c2]; a[col][c2] = a[p][c2]; a[p][c2] = t;
                }
            double pi = 1.0 / a[col][col];
            for (int c2 = 0; c2 < 8; c2++) a[col][c2] *= pi;
            for (int r = 0; r < 4; r++) if (r != col) {
                double f = a[r][col];
                for (int c2 = 0; c2 < 8; c2++) a[r][c2] -= f*a[col][c2];
            }
        }
        for (int v = 1; v < NV; v++) {
            const float* S = proj + ((size_t)b*NV + v)*16;
            for (int r = 0; r < 3; r++) {
                double pr[4];
                for (int c2 = 0; c2 < 4; c2++) {
                    double s = 0.0;
                    for (int k = 0; k < 4; k++) s += (double)S[r*4+k]*a[k][4+c2];
                    pr[c2] = s;
                }
                g_rot[b][v-1][r*3+0] = (float)pr[0];
                g_rot[b][v-1][r*3+1] = (float)pr[1];
                g_rot[b][v-1][r*3+2] = (float)pr[2];
                g_trans[b][v-1][r]   = (float)pr[3];
            }
        }
    }
}

// ---------------- transpose (V,B,C,H,W) -> (V,B,cg,H,W,4), coalesced STG.128 --
__global__ void transpose_kernel(const float* __restrict__ feat) {
    __shared__ float t[32][33];
    int vb = blockIdx.y;
    int hw0 = blockIdx.x * 32;
    const float* src = feat + (size_t)vb*NC*NHW;
    #pragma unroll
    for (int cc = threadIdx.y; cc < 32; cc += 8)
        t[cc][threadIdx.x] = src[(size_t)cc*NHW + hw0 + threadIdx.x];
    __syncthreads();
    int tx = threadIdx.x;     // pixel within group of 32
    int cg = threadIdx.y;     // 0..7
    float4 val = make_float4(t[4*cg+0][tx], t[4*cg+1][tx], t[4*cg+2][tx], t[4*cg+3][tx]);
    float4* dst = (float4*)g_featT + (size_t)vb*8*NHW + (size_t)cg*NHW + hw0 + tx;
    *dst = val;
}

// ---------------- kernel V: depth-marching variance with register tap cache ---
__global__ __launch_bounds__(256)
void var_kernel(const float* __restrict__ dvals) {
    int gid = blockIdx.x*256 + threadIdx.x;
    int w = gid % NW; int t = gid / NW;
    int h = t % NH; t /= NH;
    int cg = t & 7; int b = t >> 3;

    const ulonglong2* fb = (const ulonglong2*)g_featT;
    const ulonglong2* refp = fb + ((size_t)b*8 + cg)*NHW;
    const ulonglong2* v1p  = fb + ((size_t)(NB + b)*8 + cg)*NHW;
    const ulonglong2* v2p  = fb + ((size_t)(2*NB + b)*8 + cg)*NHW;

    const int ro = h*NW + w;
    const ulonglong2 r = __ldg(refp + ro);
    const ull rq01 = mul2(r.x, r.x), rq23 = mul2(r.y, r.y);

    float fx = (float)w, fy = (float)h;
    float rx[2], ry[2], rz[2], t0[2], t1[2], t2[2];
    #pragma unroll
    for (int v = 0; v < 2; v++) {
        rx[v] = g_rot[b][v][0]*fx + g_rot[b][v][1]*fy + g_rot[b][v][2];
        ry[v] = g_rot[b][v][3]*fx + g_rot[b][v][4]*fy + g_rot[b][v][5];
        rz[v] = g_rot[b][v][6]*fx + g_rot[b][v][7]*fy + g_rot[b][v][8];
        t0[v] = g_trans[b][v][0];
        t1[v] = g_trans[b][v][1];
        t2[v] = g_trans[b][v][2];
    }

    float cx[2] = {1e30f, 1e30f}, cy[2] = {1e30f, 1e30f};
    ulonglong2 tp[2][4];
    #pragma unroll
    for (int v = 0; v < 2; v++)
        #pragma unroll
        for (int k = 0; k < 4; k++) { tp[v][k].x = 0; tp[v][k].y = 0; }

    uint2* outp = g_varH + ((size_t)b*8 + cg)*ND*NHW + ro;
    const float* dv = dvals + b*ND;

    #pragma unroll 1
    for (int d = 0; d < ND; d++) {
        float dep = __ldg(dv + d);
        ull s01 = r.x, s23 = r.y, q01 = rq01, q23 = rq23;
        #pragma unroll
        for (int v = 0; v < 2; v++) {
            float pz = rz[v]*dep + t2[v];
            if (fabsf(pz) < 1e-6f) pz = 1e-6f;
            float px = __fdividef(rx[v]*dep + t0[v], pz);
            float py = __fdividef(ry[v]*dep + t1[v], pz);
            float x0f = floorf(px), y0f = floorf(py);
            if (x0f != cx[v] || y0f != cy[v]) {
                cx[v] = x0f; cy[v] = y0f;
                int ix0 = (int)fminf(fmaxf(x0f,       0.f), (float)(NW-1));
                int ix1 = (int)fminf(fmaxf(x0f + 1.f, 0.f), (float)(NW-1));
                int iy0 = (int)fminf(fmaxf(y0f,       0.f), (float)(NH-1));
                int iy1 = (int)fminf(fmaxf(y0f + 1.f, 0.f), (float)(NH-1));
                const ulonglong2* bp = v ? v2p : v1p;
                tp[v][0] = __ldg(bp + (iy0*NW + ix0));
                tp[v][1] = __ldg(bp + (iy0*NW + ix1));
                tp[v][2] = __ldg(bp + (iy1*NW + ix0));
                tp[v][3] = __ldg(bp + (iy1*NW + ix1));
            }
            float wx1 = px - x0f, wy1 = py - y0f;
            float wx0 = 1.f - wx1, wy0 = 1.f - wy1;
            float vx0 = (x0f >= 0.f && x0f <= (float)(NW-1)) ? 1.f : 0.f;
            float vx1 = (x0f + 1.f >= 0.f && x0f + 1.f <= (float)(NW-1)) ? 1.f : 0.f;
            float vy0 = (y0f >= 0.f && y0f <= (float)(NH-1)) ? 1.f : 0.f;
            float vy1 = (y0f + 1.f >= 0.f && y0f + 1.f <= (float)(NH-1)) ? 1.f : 0.f;
            ull W00 = dup2(wx0*wy0*vx0*vy0);
            ull W01 = dup2(wx1*wy0*vx1*vy0);
            ull W10 = dup2(wx0*wy1*vx0*vy1);
            ull W11 = dup2(wx1*wy1*vx1*vy1);
            ull a01 = mul2(tp[v][0].x, W00);
            fma2a(a01, tp[v][1].x, W01);
            fma2a(a01, tp[v][2].x, W10);
            fma2a(a01, tp[v][3].x, W11);
            ull a23 = mul2(tp[v][0].y, W00);
            fma2a(a23, tp[v][1].y, W01);
            fma2a(a23, tp[v][2].y, W10);
            fma2a(a23, tp[v][3].y, W11);
            add2a(s01, a01); fma2a(q01, a01, a01);
            add2a(s23, a23); fma2a(q23, a23, a23);
        }
        ull m;
        m = mul2(s01, INV3P); ull x01 = fma2(m ^ NEGMASK, m, mul2(q01, INV3P));
        m = mul2(s23, INV3P); ull x23 = fma2(m ^ NEGMASK, m, mul2(q23, INV3P));
        uint2 o; o.x = pkh2(x01); o.y = pkh2(x23);
        outp[(size_t)d*NHW] = o;
    }
}

// ---------------- kernel C: tiled 3^3 conv, fp32-planar smem ------------------
#define CTD 4
#define CTH 16
#define CTW 32
#define NZC (ND/CTD)         // 12
#define CHD (CTD+2)          // 6
#define CHHs (CTH+2)         // 18
#define CHWs (CTW+2)         // 34
#define CPLANE (CHHs*CHWs)   // 612
#define CVOL (CHD*CPLANE)    // 3672
// smem: sV[2 chp][CVOL] f32-pairs (ull) + weights
#define CSMEM (2*CVOL*8 + 864*4)   // 62208 -> 3 blocks/SM

__global__ __launch_bounds__(256, 3)
void conv_kernel() {
    extern __shared__ unsigned char smem_raw[];
    ull*   s0 = (ull*)smem_raw;            // chp 0 plane: f32x2 per pixel
    ull*   s1 = s0 + CVOL;                 // chp 1 plane
    float* sW = (float*)(smem_raw + 2*CVOL*8);

    const int tid = threadIdx.x;
    const int b  = blockIdx.z / NZC;
    const int d0 = (blockIdx.z - b*NZC)*CTD;
    const int h0 = blockIdx.y * CTH;
    const int w0 = blockIdx.x * CTW;

    for (int i = tid; i < 864; i += 256) sW[i] = g_wcf[i];

    const int hl = tid >> 4;        // 0..15 output row
    const int wp = (tid & 15) * 2;  // owns w = wp, wp+1

    ull acc[CTD][2];
    #pragma unroll
    for (int o = 0; o < CTD; o++) { acc[o][0] = 0; acc[o][1] = 0; }

    #pragma unroll 1
    for (int cg = 0; cg < 8; cg++) {
        // ---- load halo tile: fp16 gmem -> fp32 planar smem (convert ONCE) ----
        const uint2* gvc = g_varH + ((size_t)b*8 + cg)*ND*NHW;
        for (int i = tid; i < CVOL; i += 256) {
            int hd = i / CPLANE;
            int p  = i - hd*CPLANE;
            int hh = p / CHWs;
            int ww = p - hh*CHWs;
            int d = d0 - 1 + hd, h = h0 + hh - 1, w = w0 + ww - 1;
            uint2 v; v.x = 0; v.y = 0;
            if ((unsigned)d < (unsigned)ND && (unsigned)h < (unsigned)NH &&
                (unsigned)w < (unsigned)NW)
                v = __ldg(gvc + (size_t)d*NHW + h*NW + w);
            s0[i] = h2f2(v.x);
            s1[i] = h2f2(v.y);
        }
        __syncthreads();

        #pragma unroll 1
        for (int chp = 0; chp < 2; chp++) {
            const ull* sVc = chp ? s1 : s0;
            const ull* wb = (const ull*)sW + (cg*2 + chp)*27;
            #pragma unroll
            for (int kh = 0; kh < 3; kh++) {
                ull wk[3][3];   // [kw][kd] packed ch-pair weights
                #pragma unroll
                for (int kw = 0; kw < 3; kw++)
                    #pragma unroll
                    for (int kd = 0; kd < 3; kd++)
                        wk[kw][kd] = wb[(kh*3 + kw)*3 + kd];
                const ull* rowb = sVc + (hl + kh)*CHWs + wp;
                #pragma unroll
                for (int hd = 0; hd < CHD; hd++) {
                    // even ull index -> 16B aligned; 2x LDS.128, 4 pixels fp32
                    ulonglong2 va = *(const ulonglong2*)(rowb + hd*CPLANE);
                    ulonglong2 vb2 = *(const ulonglong2*)(rowb + hd*CPLANE + 2);
                    ull c0 = va.x, c1 = va.y, c2 = vb2.x, c3 = vb2.y;
                    #pragma unroll
                    for (int kd = 0; kd < 3; kd++) {
                        const int o = hd - kd;
                        if (o >= 0 && o < CTD) {
                            fma2a(acc[o][0], c0, wk[0][kd]);
                            fma2a(acc[o][0], c1, wk[1][kd]);
                            fma2a(acc[o][0], c2, wk[2][kd]);
                            fma2a(acc[o][1], c1, wk[0][kd]);
                            fma2a(acc[o][1], c2, wk[1][kd]);
                            fma2a(acc[o][1], c3, wk[2][kd]);
                        }
                    }
                }
            }
        }
        __syncthreads();
    }

    const float bias = g_bias;
    #pragma unroll
    for (int o = 0; o < CTD; o++) {
        size_t base = (((size_t)b*ND + d0 + o)*NH + (h0 + hl))*NW + w0 + wp;
        float2 r;
        r.x = sum2(acc[o][0]) + bias;
        r.y = sum2(acc[o][1]) + bias;
        *(float2*)(g_cost + base) = r;
    }
}

// ---------------- softmax over depth + expected depth + confidence ----------------
__global__ __launch_bounds__(256)
void softmax_kernel(const float* __restrict__ dvals, float* __restrict__ out) {
    int gid = blockIdx.x*blockDim.x + threadIdx.x;
    if (gid >= NB*NHW) return;
    int b = gid / NHW;
    int hw = gid - b*NHW;
    const float* cp = g_cost + (size_t)b*ND*NHW + hw;
    float c[ND];
    float mx = -3.4e38f;
    #pragma unroll
    for (int d = 0; d < ND; d++) {
        c[d] = cp[(size_t)d*NHW];
        mx = fmaxf(mx, c[d]);
    }
    float sum = 0.f;
    #pragma unroll
    for (int d = 0; d < ND; d++) {
        c[d] = __expf(c[d] - mx);
        sum += c[d];
    }
    float inv = 1.f/sum;
    float depth = 0.f, fidx = 0.f;
    #pragma unroll
    for (int d = 0; d < ND; d++) {
        depth += c[d]*__ldg(&dvals[b*ND + d]);
        fidx  += c[d]*(float)d;
    }
    depth *= inv;
    fidx  *= inv;
    int di = (int)fidx;
    di = min(max(di, 0), ND-1);
    float conf = 0.f;
    #pragma unroll
    for (int d = 0; d < ND; d++) {
        if (d >= di-1 && d <= di+2) conf += c[d];
    }
    conf *= inv;
    out[gid] = depth;
    out[NB*NHW + gid] = conf;
}

// ---------------- launch ----------------
extern "C" void kernel_launch(void* const* d_in, const int* in_sizes, int n_in,
                              void* d_out, int out_size) {
    const float* features = (const float*)d_in[0];   // (V,B,C,H,W)
    const float* proj     = (const float*)d_in[1];   // (B,V,4,4)
    const float* dvals    = (const float*)d_in[2];   // (B,D)
    int iw = 3;
    while (iw < n_in && in_sizes[iw] != 27*NC) iw++;
    const float* rw = (const float*)d_in[iw];
    const float* rb = (const float*)d_in[iw+1];

    cudaFuncSetAttribute(conv_kernel,
                         cudaFuncAttributeMaxDynamicSharedMemorySize, CSMEM);

    prep_kernel<<<1, 256>>>(proj, rw, rb);
    transpose_kernel<<<dim3(NHW/32, NV*NB), dim3(32, 8)>>>(features);
    var_kernel<<<(NB*8*NHW)/256, 256>>>(dvals);
    conv_kernel<<<dim3(NW/CTW, NH/CTH, NB*NZC), 256, CSMEM>>>();
    softmax_kernel<<<(NB*NHW + 255)/256, 256>>>(dvals, (float*)d_out);
}

// round 17
// speedup vs baseline: 1.0342x; 1.0342x over previous
#include <cuda_runtime.h>
#include <cuda_fp16.h>
#include <math.h>

// ---------------- problem constants ----------------
#define NB 2
#define NV 3
#define NC 32
#define ND 48
#define NH 128
#define NW 160
#define NHW (NH*NW)          // 20480

typedef unsigned long long ull;

// ---------------- device scratch ----------------
// Feature layout: (V, B, cg=8, H, W, 4ch) fp32, pixel stride 16B
__device__ __align__(128) float g_featT[(size_t)NV*NB*NHW*NC];
// Variance volume fp16: (B, cg=8, D, H, W) x 4ch packed in uint2 (2x half2)
__device__ __align__(128) uint2 g_varH[(size_t)NB*8*ND*NHW];
__device__ __align__(16) float g_cost[(size_t)NB*ND*NHW];
__device__ float g_rot[NB][2][9];
__device__ float g_trans[NB][2][3];
// conv weights as float2 per (cg,chp,kh,kw,kd)
__device__ __align__(16) float g_wcf[864];
__device__ float g_bias;
// uniform-shift fast path: per (b,v,d): {idx, idy, w00, w01, w10, w11, 0, 0}
__device__ __align__(16) float g_stab[NB][2][ND][8];
__device__ int g_fast[NB];

// ---------------- packed f32x2 helpers ----------------
__device__ __forceinline__ void fma2a(ull& c, ull a, ull b) {
    asm("fma.rn.f32x2 %0, %1, %2, %0;" : "+l"(c) : "l"(a), "l"(b));
}
__device__ __forceinline__ void add2a(ull& c, ull a) {
    asm("add.rn.f32x2 %0, %0, %1;" : "+l"(c) : "l"(a));
}
__device__ __forceinline__ ull fma2(ull a, ull b, ull c) {
    ull d; asm("fma.rn.f32x2 %0, %1, %2, %3;" : "=l"(d) : "l"(a), "l"(b), "l"(c)); return d;
}
__device__ __forceinline__ ull mul2(ull a, ull b) {
    ull d; asm("mul.rn.f32x2 %0, %1, %2;" : "=l"(d) : "l"(a), "l"(b)); return d;
}
__device__ __forceinline__ ull dup2(float f) {
    ull d; int r = __float_as_int(f);
    asm("mov.b64 %0, {%1, %1};" : "=l"(d) : "r"(r)); return d;
}
__device__ __forceinline__ float sum2(ull v) {
    int lo, hi; asm("mov.b64 {%0, %1}, %2;" : "=r"(lo), "=r"(hi) : "l"(v));
    return __int_as_float(lo) + __int_as_float(hi);
}
__device__ __forceinline__ unsigned pkh2(ull v) {
    float lo, hi;
    asm("mov.b64 {%0, %1}, %2;" : "=f"(lo), "=f"(hi) : "l"(v));
    unsigned r;
    asm("cvt.rn.f16x2.f32 %0, %1, %2;" : "=r"(r) : "f"(hi), "f"(lo));
    return r;
}
__device__ __forceinline__ ull h2f2(unsigned h) {
    float lo, hi;
    asm("{ .reg .f16 l, u; mov.b32 {l, u}, %2; cvt.f32.f16 %0, l; cvt.f32.f16 %1, u; }"
        : "=f"(lo), "=f"(hi) : "r"(h));
    ull d; asm("mov.b64 %0, {%1, %2};" : "=l"(d) : "f"(lo), "f"(hi));
    return d;
}
#define NEGMASK 0x8000000080000000ULL
#define INV3P   0x3eaaaaab3eaaaaabULL   // (1/3, 1/3)

// ---------------- prep: proj @ inv(ref_proj), weights, shift table ------------
__global__ void prep_kernel(const float* __restrict__ proj,
                            const float* __restrict__ rw,
                            const float* __restrict__ rb,
                            const float* __restrict__ dvals) {
    int tid = threadIdx.x;
    for (int i = tid; i < 27*NC; i += blockDim.x) {
        int c = i / 27, k = i - c*27;
        int kd = k / 9, kh = (k - kd*9) / 3, kw = k % 3;
        int cg = c >> 2, chp = (c >> 1) & 1, lane = c & 1;
        g_wcf[(((cg*2 + chp)*27) + (kh*3 + kw)*3 + kd)*2 + lane] = rw[i];
    }
    if (tid == 0) g_bias = rb[0];
    if (tid < NB) {
        int b = tid;
        const float* refp = proj + ((size_t)b*NV + 0)*16;
        double a[4][8];
        for (int r = 0; r < 4; r++)
            for (int c2 = 0; c2 < 4; c2++) {
                a[r][c2] = (double)refp[r*4+c2];
                a[r][4+c2] = (r == c2) ? 1.0 : 0.0;
            }
        for (int col = 0; col < 4; col++) {
            int p = col; double best = fabs(a[col][col]);
            for (int r = col+1; r < 4; r++) {
                double v = fabs(a[r][col]);
                if (v > best) { best = v; p = r; }
            }
            if (p != col)
                for (int c2 = 0; c2 < 8; c2++) {
                    double t = a[col][c2]; a[col][c2] = a[p][c2]; a[p][c2] = t;
                }
            double pi = 1.0 / a[col][col];
            for (int c2 = 0; c2 < 8; c2++) a[col][c2] *= pi;
            for (int r = 0; r < 4; r++) if (r != col) {
                double f = a[r][col];
                for (int c2 = 0; c2 < 8; c2++) a[r][c2] -= f*a[col][c2];
            }
        }
        for (int v = 1; v < NV; v++) {
            const float* S = proj + ((size_t)b*NV + v)*16;
            for (int r = 0; r < 3; r++) {
                double pr[4];
                for (int c2 = 0; c2 < 4; c2++) {
                    double s = 0.0;
                    for (int k = 0; k < 4; k++) s += (double)S[r*4+k]*a[k][4+c2];
                    pr[c2] = s;
                }
                g_rot[b][v-1][r*3+0] = (float)pr[0];
                g_rot[b][v-1][r*3+1] = (float)pr[1];
                g_rot[b][v-1][r*3+2] = (float)pr[2];
                g_trans[b][v-1][r]   = (float)pr[3];
            }
        }
        // ---- detect uniform-shift geometry and tabulate per-depth shifts ----
        int fast = 1;
        for (int v = 0; v < 2; v++) {
            const float* R = g_rot[b][v];
            float dev = fabsf(R[0]-1.f) + fabsf(R[1]) + fabsf(R[2])
                      + fabsf(R[3]) + fabsf(R[4]-1.f) + fabsf(R[5])
                      + fabsf(R[6]) + fabsf(R[7]) + fabsf(R[8]-1.f);
            if (dev > 1e-6f || fabsf(g_trans[b][v][2]) > 1e-4f) fast = 0;
        }
        g_fast[b] = fast;
        if (fast) {
            for (int v = 0; v < 2; v++) {
                float T0 = g_trans[b][v][0], T1 = g_trans[b][v][1], T2 = g_trans[b][v][2];
                float r8 = g_rot[b][v][8];
                for (int d = 0; d < ND; d++) {
                    float dep = dvals[b*ND + d];
                    float pz = r8*dep + T2;
                    float sx = T0 / pz;
                    float sy = T1 / pz;
                    float fxi = floorf(sx), fyi = floorf(sy);
                    float wx1 = sx - fxi, wy1 = sy - fyi;
                    float wx0 = 1.f - wx1, wy0 = 1.f - wy1;
                    float* e = g_stab[b][v][d];
                    e[0] = fxi; e[1] = fyi;
                    e[2] = wx0*wy0; e[3] = wx1*wy0;
                    e[4] = wx0*wy1; e[5] = wx1*wy1;
                    e[6] = 0.f; e[7] = 0.f;
                }
            }
        }
    }
}

// ---------------- transpose (V,B,C,H,W) -> (V,B,cg,H,W,4) --------------------
__global__ void transpose_kernel(const float* __restrict__ feat) {
    __shared__ float t[32][33];
    int vb = blockIdx.y;
    int hw0 = blockIdx.x * 32;
    const float* src = feat + (size_t)vb*NC*NHW;
    #pragma unroll
    for (int cc = threadIdx.y; cc < 32; cc += 8)
        t[cc][threadIdx.x] = src[(size_t)cc*NHW + hw0 + threadIdx.x];
    __syncthreads();
    int tx = threadIdx.x;
    int cg = threadIdx.y;
    float4 val = make_float4(t[4*cg+0][tx], t[4*cg+1][tx], t[4*cg+2][tx], t[4*cg+3][tx]);
    float4* dst = (float4*)g_featT + (size_t)vb*8*NHW + (size_t)cg*NHW + hw0 + tx;
    *dst = val;
}

// ---------------- kernel V: depth-marching variance ---------------------------
// Fast path: warp is a uniform per-depth shift -> table-driven descriptors,
// warp-uniform tap reloads. Fallback: general per-pixel homography (exact).
__global__ __launch_bounds__(256)
void var_kernel(const float* __restrict__ dvals) {
    __shared__ __align__(16) float sTab[2*ND*8];   // 3 KB

    int gid = blockIdx.x*256 + threadIdx.x;
    int w = gid % NW; int t = gid / NW;
    int h = t % NH; t /= NH;
    int cg = t & 7; int b = t >> 3;        // uniform per block (NHW % 256 == 0)

    const int fast = g_fast[b];
    if (fast) {
        const float* src = (const float*)g_stab[b];
        for (int i = threadIdx.x; i < 2*ND*8; i += 256) sTab[i] = src[i];
        __syncthreads();
    }

    const ulonglong2* fb = (const ulonglong2*)g_featT;
    const ulonglong2* refp = fb + ((size_t)b*8 + cg)*NHW;
    const ulonglong2* v1p  = fb + ((size_t)(NB + b)*8 + cg)*NHW;
    const ulonglong2* v2p  = fb + ((size_t)(2*NB + b)*8 + cg)*NHW;

    const int ro = h*NW + w;
    const ulonglong2 r = __ldg(refp + ro);
    const ull rq01 = mul2(r.x, r.x), rq23 = mul2(r.y, r.y);

    uint2* outp = g_varH + ((size_t)b*8 + cg)*ND*NHW + ro;

    if (fast) {
        int cIx[2] = {-100000, -100000}, cIy[2] = {0, 0};
        float vm[2][4];
        ulonglong2 tp[2][4];
        #pragma unroll 1
        for (int d = 0; d < ND; d++) {
            ull s01 = r.x, s23 = r.y, q01 = rq01, q23 = rq23;
            #pragma unroll
            for (int v = 0; v < 2; v++) {
                const float* e = sTab + (v*ND + d)*8;
                float4 e0 = *(const float4*)e;         // idx, idy, w00, w01
                float2 e1 = *(const float2*)(e + 4);   // w10, w11
                int idx = (int)e0.x, idy = (int)e0.y;
                if (idx != cIx[v] || idy != cIy[v]) {  // warp-uniform branch
                    cIx[v] = idx; cIy[v] = idy;
                    int x0 = w + idx, y0 = h + idy;
                    float vx0 = ((unsigned)x0       < (unsigned)NW) ? 1.f : 0.f;
                    float vx1 = ((unsigned)(x0 + 1) < (unsigned)NW) ? 1.f : 0.f;
                    float vy0 = ((unsigned)y0       < (unsigned)NH) ? 1.f : 0.f;
                    float vy1 = ((unsigned)(y0 + 1) < (unsigned)NH) ? 1.f : 0.f;
                    vm[v][0] = vx0*vy0; vm[v][1] = vx1*vy0;
                    vm[v][2] = vx0*vy1; vm[v][3] = vx1*vy1;
                    int ix0 = min(max(x0, 0), NW-1),  ix1 = min(max(x0+1, 0), NW-1);
                    int iy0 = min(max(y0, 0), NH-1),  iy1 = min(max(y0+1, 0), NH-1);
                    const ulonglong2* bp = v ? v2p : v1p;
                    tp[v][0] = __ldg(bp + (iy0*NW + ix0));
                    tp[v][1] = __ldg(bp + (iy0*NW + ix1));
                    tp[v][2] = __ldg(bp + (iy1*NW + ix0));
                    tp[v][3] = __ldg(bp + (iy1*NW + ix1));
                }
                ull W00 = dup2(e0.z*vm[v][0]);
                ull W01 = dup2(e0.w*vm[v][1]);
                ull W10 = dup2(e1.x*vm[v][2]);
                ull W11 = dup2(e1.y*vm[v][3]);
                ull a01 = mul2(tp[v][0].x, W00);
                fma2a(a01, tp[v][1].x, W01);
                fma2a(a01, tp[v][2].x, W10);
                fma2a(a01, tp[v][3].x, W11);
                ull a23 = mul2(tp[v][0].y, W00);
                fma2a(a23, tp[v][1].y, W01);
                fma2a(a23, tp[v][2].y, W10);
                fma2a(a23, tp[v][3].y, W11);
                add2a(s01, a01); fma2a(q01, a01, a01);
                add2a(s23, a23); fma2a(q23, a23, a23);
            }
            ull m;
            m = mul2(s01, INV3P); ull x01 = fma2(m ^ NEGMASK, m, mul2(q01, INV3P));
            m = mul2(s23, INV3P); ull x23 = fma2(m ^ NEGMASK, m, mul2(q23, INV3P));
            uint2 o; o.x = pkh2(x01); o.y = pkh2(x23);
            outp[(size_t)d*NHW] = o;
        }
        return;
    }

    // ---------------- general fallback (exact homography per pixel) ----------
    float fx = (float)w, fy = (float)h;
    float rx[2], ry[2], rz[2], t0[2], t1[2], t2[2];
    #pragma unroll
    for (int v = 0; v < 2; v++) {
        rx[v] = g_rot[b][v][0]*fx + g_rot[b][v][1]*fy + g_rot[b][v][2];
        ry[v] = g_rot[b][v][3]*fx + g_rot[b][v][4]*fy + g_rot[b][v][5];
        rz[v] = g_rot[b][v][6]*fx + g_rot[b][v][7]*fy + g_rot[b][v][8];
        t0[v] = g_trans[b][v][0];
        t1[v] = g_trans[b][v][1];
        t2[v] = g_trans[b][v][2];
    }
    float cx[2] = {1e30f, 1e30f}, cy[2] = {1e30f, 1e30f};
    ulonglong2 tp[2][4];
    #pragma unroll
    for (int v = 0; v < 2; v++)
        #pragma unroll
        for (int k = 0; k < 4; k++) { tp[v][k].x = 0; tp[v][k].y = 0; }
    const float* dv = dvals + b*ND;

    #pragma unroll 1
    for (int d = 0; d < ND; d++) {
        float dep = __ldg(dv + d);
        ull s01 = r.x, s23 = r.y, q01 = rq01, q23 = rq23;
        #pragma unroll
        for (int v = 0; v < 2; v++) {
            float pz = rz[v]*dep + t2[v];
            if (fabsf(pz) < 1e-6f) pz = 1e-6f;
            float px = __fdividef(rx[v]*dep + t0[v], pz);
            float py = __fdividef(ry[v]*dep + t1[v], pz);
            float x0f = floorf(px), y0f = floorf(py);
            if (x0f != cx[v] || y0f != cy[v]) {
                cx[v] = x0f; cy[v] = y0f;
                int ix0 = (int)fminf(fmaxf(x0f,       0.f), (float)(NW-1));
                int ix1 = (int)fminf(fmaxf(x0f + 1.f, 0.f), (float)(NW-1));
                int iy0 = (int)fminf(fmaxf(y0f,       0.f), (float)(NH-1));
                int iy1 = (int)fminf(fmaxf(y0f + 1.f, 0.f), (float)(NH-1));
                const ulonglong2* bp = v ? v2p : v1p;
                tp[v][0] = __ldg(bp + (iy0*NW + ix0));
                tp[v][1] = __ldg(bp + (iy0*NW + ix1));
                tp[v][2] = __ldg(bp + (iy1*NW + ix0));
                tp[v][3] = __ldg(bp + (iy1*NW + ix1));
            }
            float wx1 = px - x0f, wy1 = py - y0f;
            float wx0 = 1.f - wx1, wy0 = 1.f - wy1;
            float vx0 = (x0f >= 0.f && x0f <= (float)(NW-1)) ? 1.f : 0.f;
            float vx1 = (x0f + 1.f >= 0.f && x0f + 1.f <= (float)(NW-1)) ? 1.f : 0.f;
            float vy0 = (y0f >= 0.f && y0f <= (float)(NH-1)) ? 1.f : 0.f;
            float vy1 = (y0f + 1.f >= 0.f && y0f + 1.f <= (float)(NH-1)) ? 1.f : 0.f;
            ull W00 = dup2(wx0*wy0*vx0*vy0);
            ull W01 = dup2(wx1*wy0*vx1*vy0);
            ull W10 = dup2(wx0*wy1*vx0*vy1);
            ull W11 = dup2(wx1*wy1*vx1*vy1);
            ull a01 = mul2(tp[v][0].x, W00);
            fma2a(a01, tp[v][1].x, W01);
            fma2a(a01, tp[v][2].x, W10);
            fma2a(a01, tp[v][3].x, W11);
            ull a23 = mul2(tp[v][0].y, W00);
            fma2a(a23, tp[v][1].y, W01);
            fma2a(a23, tp[v][2].y, W10);
            fma2a(a23, tp[v][3].y, W11);
            add2a(s01, a01); fma2a(q01, a01, a01);
            add2a(s23, a23); fma2a(q23, a23, a23);
        }
        ull m;
        m = mul2(s01, INV3P); ull x01 = fma2(m ^ NEGMASK, m, mul2(q01, INV3P));
        m = mul2(s23, INV3P); ull x23 = fma2(m ^ NEGMASK, m, mul2(q23, INV3P));
        uint2 o; o.x = pkh2(x01); o.y = pkh2(x23);
        outp[(size_t)d*NHW] = o;
    }
}

// ---------------- kernel C: tiled 3^3 conv, fp32-planar smem ------------------
#define CTD 4
#define CTH 16
#define CTW 32
#define NZC (ND/CTD)         // 12
#define CHD (CTD+2)          // 6
#define CHHs (CTH+2)         // 18
#define CHWs (CTW+2)         // 34
#define CPLANE (CHHs*CHWs)   // 612
#define CVOL (CHD*CPLANE)    // 3672
#define CSMEM (2*CVOL*8 + 864*4)   // 62208 -> 3 blocks/SM

__global__ __launch_bounds__(256, 3)
void conv_kernel() {
    extern __shared__ unsigned char smem_raw[];
    ull*   s0 = (ull*)smem_raw;
    ull*   s1 = s0 + CVOL;
    float* sW = (float*)(smem_raw + 2*CVOL*8);

    const int tid = threadIdx.x;
    const int b  = blockIdx.z / NZC;
    const int d0 = (blockIdx.z - b*NZC)*CTD;
    const int h0 = blockIdx.y * CTH;
    const int w0 = blockIdx.x * CTW;

    for (int i = tid; i < 864; i += 256) sW[i] = g_wcf[i];

    const int hl = tid >> 4;
    const int wp = (tid & 15) * 2;

    ull acc[CTD][2];
    #pragma unroll
    for (int o = 0; o < CTD; o++) { acc[o][0] = 0; acc[o][1] = 0; }

    #pragma unroll 1
    for (int cg = 0; cg < 8; cg++) {
        const uint2* gvc = g_varH + ((size_t)b*8 + cg)*ND*NHW;
        for (int i = tid; i < CVOL; i += 256) {
            int hd = i / CPLANE;
            int p  = i - hd*CPLANE;
            int hh = p / CHWs;
            int ww = p - hh*CHWs;
            int d = d0 - 1 + hd, h = h0 + hh - 1, w = w0 + ww - 1;
            uint2 v; v.x = 0; v.y = 0;
            if ((unsigned)d < (unsigned)ND && (unsigned)h < (unsigned)NH &&
                (unsigned)w < (unsigned)NW)
                v = __ldg(gvc + (size_t)d*NHW + h*NW + w);
            s0[i] = h2f2(v.x);
            s1[i] = h2f2(v.y);
        }
        __syncthreads();

        #pragma unroll 1
        for (int chp = 0; chp < 2; chp++) {
            const ull* sVc = chp ? s1 : s0;
            const ull* wb = (const ull*)sW + (cg*2 + chp)*27;
            #pragma unroll
            for (int kh = 0; kh < 3; kh++) {
                ull wk[3][3];
                #pragma unroll
                for (int kw = 0; kw < 3; kw++)
                    #pragma unroll
                    for (int kd = 0; kd < 3; kd++)
                        wk[kw][kd] = wb[(kh*3 + kw)*3 + kd];
                const ull* rowb = sVc + (hl + kh)*CHWs + wp;
                #pragma unroll
                for (int hd = 0; hd < CHD; hd++) {
                    ulonglong2 va = *(const ulonglong2*)(rowb + hd*CPLANE);
                    ulonglong2 vb2 = *(const ulonglong2*)(rowb + hd*CPLANE + 2);
                    ull c0 = va.x, c1 = va.y, c2 = vb2.x, c3 = vb2.y;
                    #pragma unroll
                    for (int kd = 0; kd < 3; kd++) {
                        const int o = hd - kd;
                        if (o >= 0 && o < CTD) {
                            fma2a(acc[o][0], c0, wk[0][kd]);
                            fma2a(acc[o][0], c1, wk[1][kd]);
                            fma2a(acc[o][0], c2, wk[2][kd]);
                            fma2a(acc[o][1], c1, wk[0][kd]);
                            fma2a(acc[o][1], c2, wk[1][kd]);
                            fma2a(acc[o][1], c3, wk[2][kd]);
                        }
                    }
                }
            }
        }
        __syncthreads();
    }

    const float bias = g_bias;
    #pragma unroll
    for (int o = 0; o < CTD; o++) {
        size_t base = (((size_t)b*ND + d0 + o)*NH + (h0 + hl))*NW + w0 + wp;
        float2 r;
        r.x = sum2(acc[o][0]) + bias;
        r.y = sum2(acc[o][1]) + bias;
        *(float2*)(g_cost + base) = r;
    }
}

// ---------------- softmax over depth + expected depth + confidence ------------
__global__ __launch_bounds__(256)
void softmax_kernel(const float* __restrict__ dvals, float* __restrict__ out) {
    int gid = blockIdx.x*blockDim.x + threadIdx.x;
    if (gid >= NB*NHW) return;
    int b = gid / NHW;
    int hw = gid - b*NHW;
    const float* cp = g_cost + (size_t)b*ND*NHW + hw;
    float c[ND];
    float mx = -3.4e38f;
    #pragma unroll
    for (int d = 0; d < ND; d++) {
        c[d] = cp[(size_t)d*NHW];
        mx = fmaxf(mx, c[d]);
    }
    float sum = 0.f;
    #pragma unroll
    for (int d = 0; d < ND; d++) {
        c[d] = __expf(c[d] - mx);
        sum += c[d];
    }
    float inv = 1.f/sum;
    float depth = 0.f, fidx = 0.f;
    #pragma unroll
    for (int d = 0; d < ND; d++) {
        depth += c[d]*__ldg(&dvals[b*ND + d]);
        fidx  += c[d]*(float)d;
    }
    depth *= inv;
    fidx  *= inv;
    int di = (int)fidx;
    di = min(max(di, 0), ND-1);
    float conf = 0.f;
    #pragma unroll
    for (int d = 0; d < ND; d++) {
        if (d >= di-1 && d <= di+2) conf += c[d];
    }
    conf *= inv;
    out[gid] = depth;
    out[NB*NHW + gid] = conf;
}

// ---------------- launch ----------------
extern "C" void kernel_launch(void* const* d_in, const int* in_sizes, int n_in,
                              void* d_out, int out_size) {
    const float* features = (const float*)d_in[0];   // (V,B,C,H,W)
    const float* proj     = (const float*)d_in[1];   // (B,V,4,4)
    const float* dvals    = (const float*)d_in[2];   // (B,D)
    int iw = 3;
    while (iw < n_in && in_sizes[iw] != 27*NC) iw++;
    const float* rw = (const float*)d_in[iw];
    const float* rb = (const float*)d_in[iw+1];

    cudaFuncSetAttribute(conv_kernel,
                         cudaFuncAttributeMaxDynamicSharedMemorySize, CSMEM);

    prep_kernel<<<1, 256>>>(proj, rw, rb, dvals);
    transpose_kernel<<<dim3(NHW/32, NV*NB), dim3(32, 8)>>>(features);
    var_kernel<<<(NB*8*NHW)/256, 256>>>(dvals);
    conv_kernel<<<dim3(NW/CTW, NH/CTH, NB*NZC), 256, CSMEM>>>();
    softmax_kernel<<<(NB*NHW + 255)/256, 256>>>(dvals, (float*)d_out);
}